// round 14
// baseline (speedup 1.0000x reference)
#include <cuda_runtime.h>
#include <cstdint>

#define BB 4096
#define DD 784
#define DHALF 392
#define HH 16
#define LL 4
#define RR 4
#define KK 8
#define ITILE 8
#define NBI 49      /* 392 / 8 */
#define BTILE 32    /* invert: rows per block (2 per thread) */
#define WPAD 1188   /* padded row length for transposed W_in in smem */
#define WTS 28      /* padded per-(k,ti) row stride in invert Wt tile */
#define NSOLVE 8    /* fixed solver iterations, no early exit */
#define CBLK 512    /* cond_k block size: 16 warps x 2 rows = 32 rows/block */
#define LOG2PI_F 1.8378770664093453f
#define LOG2E_F 1.4426950408889634f
#define LN2_F 0.6931471805599453f

// scratch (no allocations allowed)
__device__ float g_h[BB * HH];
__device__ float g_ldpart[NBI * BB];   // [j][b] transposed for coalesced access

__device__ __forceinline__ float frcp(float x) {
    float r; asm("rcp.approx.ftz.f32 %0, %1;" : "=f"(r) : "f"(x)); return r;
}
__device__ __forceinline__ float fexp2(float x) {
    float r; asm("ex2.approx.ftz.f32 %0, %1;" : "=f"(r) : "f"(x)); return r;
}
__device__ __forceinline__ float flog2(float x) {
    float r; asm("lg2.approx.ftz.f32 %0, %1;" : "=f"(r) : "f"(x)); return r;
}
__device__ __forceinline__ float fexpf_(float x) { return fexp2(x * LOG2E_F); }
__device__ __forceinline__ float flogf_(float x) { return flog2(x) * LN2_F; }

// packed fp32x2 helpers (sm_103a dual-fp32 pipe)
__device__ __forceinline__ uint64_t pk2(float lo, float hi) {
    uint64_t r; asm("mov.b64 %0, {%1, %2};" : "=l"(r) : "f"(lo), "f"(hi)); return r;
}
__device__ __forceinline__ void upk2(float& lo, float& hi, uint64_t v) {
    asm("mov.b64 {%0, %1}, %2;" : "=f"(lo), "=f"(hi) : "l"(v));
}
__device__ __forceinline__ uint64_t ffma2_(uint64_t a, uint64_t b, uint64_t c) {
    uint64_t d; asm("fma.rn.f32x2 %0, %1, %2, %3;" : "=l"(d) : "l"(a), "l"(b), "l"(c)); return d;
}
__device__ __forceinline__ uint64_t fmul2_(uint64_t a, uint64_t b) {
    uint64_t d; asm("mul.rn.f32x2 %0, %1, %2;" : "=l"(d) : "l"(a), "l"(b)); return d;
}
__device__ __forceinline__ uint64_t fadd2_(uint64_t a, uint64_t b) {
    uint64_t d; asm("add.rn.f32x2 %0, %1, %2;" : "=l"(d) : "l"(a), "l"(b)); return d;
}

// ---------------------------------------------------------------------------
// init (float4-vectorized copy + squared-sum)
// ---------------------------------------------------------------------------
__global__ void __launch_bounds__(256) init_k(const float* __restrict__ eps,
                                              float* __restrict__ z,
                                              float* __restrict__ lq) {
    int b = blockIdx.x;
    const float4* e4 = (const float4*)(eps + (size_t)b * DD);
    float4* z4 = (float4*)(z + (size_t)b * DD);
    float s = 0.f;
    if (threadIdx.x < 196) {
        float4 v = e4[threadIdx.x];
        z4[threadIdx.x] = v;
        s = v.x * v.x + v.y * v.y + v.z * v.z + v.w * v.w;
    }
    __shared__ float red[256];
    red[threadIdx.x] = s;
    __syncthreads();
    for (int o = 128; o > 0; o >>= 1) {
        if (threadIdx.x < o) red[threadIdx.x] += red[threadIdx.x + o];
        __syncthreads();
    }
    if (threadIdx.x == 0) lq[b] = -0.5f * (red[0] + (float)DD * LOG2PI_F);
    if (threadIdx.x < NBI) g_ldpart[(size_t)threadIdx.x * BB + b] = 0.f;
}

// ---------------------------------------------------------------------------
// conditioner: 512 threads (16 warps x 2 rows = 32 rows/block), grid 128.
// ---------------------------------------------------------------------------
__global__ void __launch_bounds__(CBLK) cond_k(const float* __restrict__ z,
                                               const float* __restrict__ x,
                                               const float* __restrict__ Win,
                                               const float* __restrict__ bin,
                                               const float* __restrict__ W1,
                                               const float* __restrict__ b1v,
                                               const float* __restrict__ W2,
                                               const float* __restrict__ b2v,
                                               int zb_off) {
    extern __shared__ float sm[];
    float* Ws = sm;                       // 16 * WPAD (transposed)
    float* W1s = Ws + 16 * WPAD;          // 1024
    float* W2s = W1s + 1024;              // 1024
    float* b1s = W2s + 1024;              // 64
    float* b2s = b1s + 64;                // 64
    float* bis = b2s + 64;                // 16

    for (int idx = threadIdx.x; idx < 1176 * 16; idx += CBLK) {
        int k = idx >> 4, j = idx & 15;
        Ws[j * WPAD + k] = Win[idx];
    }
    for (int idx = threadIdx.x; idx < 16 * (WPAD - 1176); idx += CBLK) {
        int j = idx / (WPAD - 1176), c = idx % (WPAD - 1176);
        Ws[j * WPAD + 1176 + c] = 0.f;
    }
    for (int i = threadIdx.x; i < 1024; i += CBLK) { W1s[i] = W1[i]; W2s[i] = W2[i]; }
    if (threadIdx.x < 64) { b1s[threadIdx.x] = b1v[threadIdx.x]; b2s[threadIdx.x] = b2v[threadIdx.x]; }
    else if (threadIdx.x >= 64 && threadIdx.x < 80) bis[threadIdx.x - 64] = bin[threadIdx.x - 64];
    __syncthreads();

    int warp = threadIdx.x >> 5, lane = threadIdx.x & 31;
    int b0 = blockIdx.x * 32 + warp * 2;
    const float4* z0 = (const float4*)(z + (size_t)b0 * DD + zb_off);
    const float4* z1 = (const float4*)(z + (size_t)(b0 + 1) * DD + zb_off);
    const float4* x0 = (const float4*)(x + (size_t)b0 * DD);
    const float4* x1 = (const float4*)(x + (size_t)(b0 + 1) * DD);

    float a0[16], a1[16];
#pragma unroll
    for (int j = 0; j < 16; ++j) { a0[j] = 0.f; a1[j] = 0.f; }

#pragma unroll
    for (int t = 0; t < 10; ++t) {
        int k = lane * 4 + t * 128;
        if (k < 1176) {
            float4 v0 = (k < DHALF) ? z0[k >> 2] : x0[(k - DHALF) >> 2];
            float4 v1 = (k < DHALF) ? z1[k >> 2] : x1[(k - DHALF) >> 2];
#pragma unroll
            for (int j = 0; j < 16; ++j) {
                float4 wv = *(const float4*)(Ws + j * WPAD + k);
                a0[j] = fmaf(v0.x, wv.x, fmaf(v0.y, wv.y, fmaf(v0.z, wv.z, fmaf(v0.w, wv.w, a0[j]))));
                a1[j] = fmaf(v1.x, wv.x, fmaf(v1.y, wv.y, fmaf(v1.z, wv.z, fmaf(v1.w, wv.w, a1[j]))));
            }
        }
    }

    bool up16 = (lane & 16);
    float v[16];
#pragma unroll
    for (int j = 0; j < 16; ++j) {
        float send = up16 ? a0[j] : a1[j];
        float got = __shfl_xor_sync(0xffffffffu, send, 16);
        v[j] = (up16 ? a1[j] : a0[j]) + got;
    }
    // ownership tree: lane ends with its row's full sum for j = lane & 15
#pragma unroll
    for (int o = 8; o >= 1; o >>= 1) {
        bool up = (lane & o);
#pragma unroll
        for (int j = 0; j < o; ++j) {
            float keep = up ? v[j + o] : v[j];
            float send = up ? v[j] : v[j + o];
            v[j] = keep + __shfl_xor_sync(0xffffffffu, send, o);
        }
    }
    int j = lane & 15;
    float hv = v[0] + bis[j];
    float h = hv * frcp(1.f + fexpf_(-hv));

#pragma unroll
    for (int r = 0; r < RR; ++r) {
        float a = b1s[r * 16 + j];
#pragma unroll
        for (int k = 0; k < 16; ++k) {
            float hk = __shfl_sync(0xffffffffu, h, k, 16);
            a = fmaf(hk, W1s[(r * 16 + k) * 16 + j], a);
        }
        float tsw = a * frcp(1.f + fexpf_(-a));
        float a2 = b2s[r * 16 + j];
#pragma unroll
        for (int k = 0; k < 16; ++k) {
            float tk = __shfl_sync(0xffffffffu, tsw, k, 16);
            a2 = fmaf(tk, W2s[(r * 16 + k) * 16 + j], a2);
        }
        h += a2;
    }
    g_h[(size_t)(b0 + (lane >> 4)) * 16 + j] = h;
}

// ---------------------------------------------------------------------------
// fused W_out projection (f32x2) + fixed-count tanh-form solver where
// T = tanh(t/2) is computed EXACTLY as (1-E)/(1+E), E = exp(-t) via ex2
// (rt 8) + one pairwise rcp: per pair MUFU 32 -> 24 cyc, extra scalar work
// lands on the under-used FMA/ALU pipes. Same iteration (S, Gp, safeguard,
// constants), more accurate T. Accurate 2-eval polish unchanged (shares the
// eA2/eB2 exponent constants — E is the same quantity).
// ---------------------------------------------------------------------------
__global__ void __launch_bounds__(128) invert_k(float* __restrict__ z,
                                                const float* __restrict__ Wout,
                                                const float* __restrict__ bout,
                                                int za_off) {
    __shared__ float Wt[16 * 8 * WTS];   // [k][ti][28] padded, conflict-free
    __shared__ float bos[192];
    __shared__ float hsh[BTILE * 17];
    __shared__ float red[BTILE * 8];

    int i0 = blockIdx.x * ITILE;
    int b0 = blockIdx.y * BTILE;

    for (int idx = threadIdx.x; idx < 16 * 192; idx += 128) {
        int k = idx / 192, c = idx - k * 192;
        int ti = c / 24, jj = c - ti * 24;
        Wt[(k * 8 + ti) * WTS + jj] = Wout[(size_t)k * 9408 + i0 * 24 + c];
    }
    for (int idx = threadIdx.x; idx < 192; idx += 128) bos[idx] = bout[i0 * 24 + idx];
    for (int idx = threadIdx.x; idx < BTILE * 16; idx += 128) {
        int tb = idx >> 4, k = idx & 15;
        hsh[tb * 17 + k] = g_h[(size_t)(b0 + tb) * 16 + k];
    }
    __syncthreads();

    int ti = threadIdx.x & 7, tb = threadIdx.x >> 3;
    int i = i0 + ti;

    // ---- joint projection for both elements (shared Wt reads) ----
    uint64_t pA[12], pB[12];
    {
        const uint64_t* bb = (const uint64_t*)(bos + ti * 24);
#pragma unroll
        for (int jj = 0; jj < 12; ++jj) { pA[jj] = bb[jj]; pB[jj] = bb[jj]; }
#pragma unroll
        for (int k = 0; k < 16; ++k) {
            float ha = hsh[tb * 17 + k];
            float hb = hsh[(tb + 16) * 17 + k];
            uint64_t h2a = pk2(ha, ha), h2b = pk2(hb, hb);
            const ulonglong2* wr = (const ulonglong2*)(Wt + (k * 8 + ti) * WTS);
#pragma unroll
            for (int c = 0; c < 6; ++c) {
                ulonglong2 wv = wr[c];
                pA[2 * c]     = ffma2_(h2a, wv.x, pA[2 * c]);
                pA[2 * c + 1] = ffma2_(h2a, wv.y, pA[2 * c + 1]);
                pB[2 * c]     = ffma2_(h2b, wv.x, pB[2 * c]);
                pB[2 * c + 1] = ffma2_(h2b, wv.y, pB[2 * c + 1]);
            }
        }
    }

#pragma unroll
    for (int e = 0; e < 2; ++e) {
        int b = b0 + tb + (e << 4);

        float p[24];
#pragma unroll
        for (int jj = 0; jj < 12; ++jj)
            upk2(p[2 * jj], p[2 * jj + 1], e ? pB[jj] : pA[jj]);

        float y = z[(size_t)b * DD + za_off + i];

        // unnormalized softmax weights
        float lm = p[0];
#pragma unroll
        for (int k = 1; k < 8; ++k) lm = fmaxf(lm, p[k]);
        float w[8];
        float wsum = 0.f;
#pragma unroll
        for (int k = 0; k < 8; ++k) { w[k] = fexpf_(p[k] - lm); wsum += w[k]; }
        float rw = frcp(wsum);

        // packed per-pair constants + bracket + weighted initial guess.
        //   arg = -t*log2(e) = x*(-einv*L2E) + mu*einv*L2E -> one ffma2/eval
        uint64_t eA2[4], eB2[4], w2p[4], we2[4], ei2[4];
        float sumwe = 0.f, cwsum = 0.f;
        float lo = 1e30f, hi = -1e30f;
#pragma unroll
        for (int q = 0; q < 4; ++q) {
            int k0 = 2 * q, k1 = 2 * q + 1;
            float mu0 = p[8 + k0], mu1 = p[8 + k1];
            float ls0 = p[16 + k0], ls1 = p[16 + k1];
            float e0 = fexpf_(-ls0), e1 = fexpf_(-ls1);   // einv = 1/s
            float R = frcp(e0 * e1);
            float s0 = R * e1, s1 = R * e0;
            eA2[q] = pk2(-e0 * LOG2E_F, -e1 * LOG2E_F);
            eB2[q] = pk2(mu0 * e0 * LOG2E_F, mu1 * e1 * LOG2E_F);
            ei2[q] = pk2(e0, e1);
            w2p[q] = pk2(w[k0], w[k1]);
            float we0 = w[k0] * e0 * 0.5f, we1 = w[k1] * e1 * 0.5f;
            we2[q] = pk2(we0, we1);
            sumwe += we0 + we1;
            float c0 = fmaf(y, s0, mu0), c1 = fmaf(y, s1, mu1);
            cwsum += w[k0] * c0 + w[k1] * c1;
            lo = fminf(lo, fminf(c0, c1));
            hi = fmaxf(hi, fmaxf(c0, c1));
        }
        lo -= 0.015625f;
        hi += 0.015625f;
        lo = fminf(fmaxf(lo, -100.f), 100.f);
        hi = fmaxf(fminf(hi, 100.f), lo);

        // accurate tanh(y/2)*Wsum target
        float tyW;
        {
            float ey = fexpf_(fminf(y, 80.f));
            tyW = (ey - 1.f) * frcp(ey + 1.f) * wsum;
        }
        float xv = fminf(fmaxf(cwsum * rw, lo), hi);

        // fixed-count safeguarded Newton on
        //   G(x) = sum w_k tanh((x-mu_k)/(2 s_k)) - tanh(y/2)*Wsum
        // with T = (1-E)/(1+E), E = 2^arg (pairwise rcp)
#pragma unroll 1
        for (int it = 0; it < NSOLVE; ++it) {
            uint64_t xv2 = pk2(xv, xv);
            uint64_t S2 = 0ull, GB2 = 0ull;
#pragma unroll
            for (int q = 0; q < 4; ++q) {
                uint64_t arg2 = ffma2_(xv2, eA2[q], eB2[q]);
                float g0, g1; upk2(g0, g1, arg2);
                float E0 = fexp2(fminf(g0, 60.f));
                float E1 = fexp2(fminf(g1, 60.f));
                float d0 = 1.f + E0, d1 = 1.f + E1;
                float R = frcp(d0 * d1);
                float T0 = (1.f - E0) * (R * d1);
                float T1 = (1.f - E1) * (R * d0);
                uint64_t T2 = pk2(T0, T1);
                S2 = ffma2_(w2p[q], T2, S2);
                GB2 = ffma2_(we2[q], fmul2_(T2, T2), GB2);
            }
            float sl, sh, gl, gh;
            upk2(sl, sh, S2); upk2(gl, gh, GB2);
            float S = (sl + sh) - tyW;
            float Gp = sumwe - (gl + gh);
            lo = (S < 0.f) ? xv : lo;
            hi = (S < 0.f) ? hi : xv;
            float xn = xv - S * frcp(Gp);
            float xm = 0.5f * (lo + hi);
            bool ok = (xn > lo) && (xn < hi);
            xv = ok ? xn : xm;
        }

        // accurate polish: eval1 = Newton; eval2 = Newton + logdet.
        // shares eA2/eB2 (arg = -t*log2e) and ei2 (einv) with the solver.
        float ld = 0.f;
#pragma unroll 1
        for (int it = 0; it < 2; ++it) {
            uint64_t xv2 = pk2(xv, xv);
            float cdf = 0.f, sf = 0.f, pdf = 0.f;
#pragma unroll
            for (int q = 0; q < 4; ++q) {
                uint64_t arg2 = ffma2_(xv2, eA2[q], eB2[q]);
                float g0, g1; upk2(g0, g1, arg2);
                float E0 = fexp2(fminf(g0, 60.f));
                float E1 = fexp2(fminf(g1, 60.f));
                float d0 = 1.f + E0, d1 = 1.f + E1;
                float R = frcp(d0 * d1);
                float r0 = R * d1, r1 = R * d0;
                float w0, w1, i0v, i1v;
                upk2(w0, w1, w2p[q]);
                upk2(i0v, i1v, ei2[q]);
                float a0 = w0 * r0, t10 = a0 * E0;
                float a1 = w1 * r1, t11 = a1 * E1;
                cdf += a0 + a1;
                sf += t10 + t11;
                pdf = fmaf(t10 * r0, i0v, fmaf(t11 * r1, i1v, pdf));
            }
            float lc = flogf_(cdf), lsf = flogf_(sf);
            if (it == 1) ld = flogf_(pdf) - lc - lsf + flogf_(wsum);
            float f = lc - lsf - y;
            xv -= f * cdf * sf * frcp(pdf) * rw;
        }

        z[(size_t)b * DD + za_off + i] = xv;
        red[(tb + (e << 4)) * 8 + ti] = ld;
    }

    __syncthreads();
    if (threadIdx.x < BTILE) {
        const float* rr = red + threadIdx.x * 8;
        float s = rr[0] + rr[1] + rr[2] + rr[3] + rr[4] + rr[5] + rr[6] + rr[7];
        g_ldpart[(size_t)blockIdx.x * BB + b0 + threadIdx.x] += s;
    }
}

// ---------------------------------------------------------------------------
// finalize log_q (coalesced over transposed ldpart)
// ---------------------------------------------------------------------------
__global__ void __launch_bounds__(256) fin_k(float* __restrict__ lq) {
    int b = blockIdx.x * 256 + threadIdx.x;
    if (b < BB) {
        float s = lq[b];
#pragma unroll 1
        for (int j = 0; j < NBI; ++j) s += g_ldpart[(size_t)j * BB + b];
        lq[b] = s;
    }
}

extern "C" void kernel_launch(void* const* d_in, const int* in_sizes, int n_in,
                              void* d_out, int out_size) {
    (void)in_sizes; (void)n_in; (void)out_size;
    const float* x    = (const float*)d_in[0];
    const float* eps  = (const float*)d_in[1];
    const float* Win  = (const float*)d_in[2];
    const float* bin  = (const float*)d_in[3];
    const float* W1   = (const float*)d_in[4];
    const float* b1   = (const float*)d_in[5];
    const float* W2   = (const float*)d_in[6];
    const float* b2   = (const float*)d_in[7];
    const float* Wout = (const float*)d_in[8];
    const float* bout = (const float*)d_in[9];

    float* z = (float*)d_out;              // (B, D) working/output z
    float* lq = z + (size_t)BB * DD;       // (B,) log_q

    size_t smemA = (size_t)(16 * WPAD + 1024 + 1024 + 64 + 64 + 16) * sizeof(float);
    static int smem_set = 0;
    if (!smem_set) {
        cudaFuncSetAttribute((const void*)cond_k, cudaFuncAttributeMaxDynamicSharedMemorySize,
                             (int)smemA);
        smem_set = 1;
    }

    init_k<<<BB, 256>>>(eps, z, lq);

    for (int l = LL - 1; l >= 0; --l) {
        int za_off = (l & 1) ? DHALF : 0;
        int zb_off = (l & 1) ? 0 : DHALF;
        cond_k<<<BB / 32, CBLK, smemA>>>(z, x,
                                         Win + (size_t)l * 1176 * 16,
                                         bin + (size_t)l * 16,
                                         W1 + (size_t)l * RR * 256,
                                         b1 + (size_t)l * RR * 16,
                                         W2 + (size_t)l * RR * 256,
                                         b2 + (size_t)l * RR * 16,
                                         zb_off);
        invert_k<<<dim3(NBI, BB / BTILE), 128>>>(z,
                                                 Wout + (size_t)l * 16 * 9408,
                                                 bout + (size_t)l * 9408,
                                                 za_off);
    }

    fin_k<<<BB / 256, 256>>>(lq);
}

// round 15
// speedup vs baseline: 1.0815x; 1.0815x over previous
#include <cuda_runtime.h>
#include <cstdint>

#define BB 4096
#define DD 784
#define DHALF 392
#define HH 16
#define LL 4
#define RR 4
#define KK 8
#define ITILE 8
#define NBI 49      /* 392 / 8 */
#define BTILE 32    /* invert: rows per block (2 per thread) */
#define WPAD 1188   /* padded row length for transposed W_in in smem */
#define WTS 28      /* padded per-(k,ti) row stride in invert Wt tile */
#define NSOLVE 8    /* fixed solver iterations, no early exit */
#define CBLK 512    /* cond_k block size: 16 warps x 2 rows = 32 rows/block */
#define LOG2PI_F 1.8378770664093453f
#define LOG2E_F 1.4426950408889634f
#define LN2_F 0.6931471805599453f

// scratch (no allocations allowed)
__device__ float g_h[BB * HH];
__device__ float g_ldpart[NBI * BB];   // [j][b] transposed for coalesced access

__device__ __forceinline__ float frcp(float x) {
    float r; asm("rcp.approx.ftz.f32 %0, %1;" : "=f"(r) : "f"(x)); return r;
}
__device__ __forceinline__ float fexp2(float x) {
    float r; asm("ex2.approx.ftz.f32 %0, %1;" : "=f"(r) : "f"(x)); return r;
}
__device__ __forceinline__ float flog2(float x) {
    float r; asm("lg2.approx.ftz.f32 %0, %1;" : "=f"(r) : "f"(x)); return r;
}
__device__ __forceinline__ float ftanh(float x) {
    float r; asm("tanh.approx.f32 %0, %1;" : "=f"(r) : "f"(x)); return r;
}
__device__ __forceinline__ float fexpf_(float x) { return fexp2(x * LOG2E_F); }
__device__ __forceinline__ float flogf_(float x) { return flog2(x) * LN2_F; }

// packed fp32x2 helpers (sm_103a dual-fp32 pipe)
__device__ __forceinline__ uint64_t pk2(float lo, float hi) {
    uint64_t r; asm("mov.b64 %0, {%1, %2};" : "=l"(r) : "f"(lo), "f"(hi)); return r;
}
__device__ __forceinline__ void upk2(float& lo, float& hi, uint64_t v) {
    asm("mov.b64 {%0, %1}, %2;" : "=f"(lo), "=f"(hi) : "l"(v));
}
__device__ __forceinline__ uint64_t ffma2_(uint64_t a, uint64_t b, uint64_t c) {
    uint64_t d; asm("fma.rn.f32x2 %0, %1, %2, %3;" : "=l"(d) : "l"(a), "l"(b), "l"(c)); return d;
}
__device__ __forceinline__ uint64_t fmul2_(uint64_t a, uint64_t b) {
    uint64_t d; asm("mul.rn.f32x2 %0, %1, %2;" : "=l"(d) : "l"(a), "l"(b)); return d;
}

// ---------------------------------------------------------------------------
// init (float4-vectorized copy + squared-sum)
// ---------------------------------------------------------------------------
__global__ void __launch_bounds__(256) init_k(const float* __restrict__ eps,
                                              float* __restrict__ z,
                                              float* __restrict__ lq) {
    int b = blockIdx.x;
    const float4* e4 = (const float4*)(eps + (size_t)b * DD);
    float4* z4 = (float4*)(z + (size_t)b * DD);
    float s = 0.f;
    if (threadIdx.x < 196) {
        float4 v = e4[threadIdx.x];
        z4[threadIdx.x] = v;
        s = v.x * v.x + v.y * v.y + v.z * v.z + v.w * v.w;
    }
    __shared__ float red[256];
    red[threadIdx.x] = s;
    __syncthreads();
    for (int o = 128; o > 0; o >>= 1) {
        if (threadIdx.x < o) red[threadIdx.x] += red[threadIdx.x + o];
        __syncthreads();
    }
    if (threadIdx.x == 0) lq[b] = -0.5f * (red[0] + (float)DD * LOG2PI_F);
    if (threadIdx.x < NBI) g_ldpart[(size_t)threadIdx.x * BB + b] = 0.f;
}

// ---------------------------------------------------------------------------
// conditioner: 512 threads (16 warps x 2 rows = 32 rows/block), grid 128.
// ---------------------------------------------------------------------------
__global__ void __launch_bounds__(CBLK) cond_k(const float* __restrict__ z,
                                               const float* __restrict__ x,
                                               const float* __restrict__ Win,
                                               const float* __restrict__ bin,
                                               const float* __restrict__ W1,
                                               const float* __restrict__ b1v,
                                               const float* __restrict__ W2,
                                               const float* __restrict__ b2v,
                                               int zb_off) {
    extern __shared__ float sm[];
    float* Ws = sm;                       // 16 * WPAD (transposed)
    float* W1s = Ws + 16 * WPAD;          // 1024
    float* W2s = W1s + 1024;              // 1024
    float* b1s = W2s + 1024;              // 64
    float* b2s = b1s + 64;                // 64
    float* bis = b2s + 64;                // 16

    for (int idx = threadIdx.x; idx < 1176 * 16; idx += CBLK) {
        int k = idx >> 4, j = idx & 15;
        Ws[j * WPAD + k] = Win[idx];
    }
    for (int idx = threadIdx.x; idx < 16 * (WPAD - 1176); idx += CBLK) {
        int j = idx / (WPAD - 1176), c = idx % (WPAD - 1176);
        Ws[j * WPAD + 1176 + c] = 0.f;
    }
    for (int i = threadIdx.x; i < 1024; i += CBLK) { W1s[i] = W1[i]; W2s[i] = W2[i]; }
    if (threadIdx.x < 64) { b1s[threadIdx.x] = b1v[threadIdx.x]; b2s[threadIdx.x] = b2v[threadIdx.x]; }
    else if (threadIdx.x >= 64 && threadIdx.x < 80) bis[threadIdx.x - 64] = bin[threadIdx.x - 64];
    __syncthreads();

    int warp = threadIdx.x >> 5, lane = threadIdx.x & 31;
    int b0 = blockIdx.x * 32 + warp * 2;
    const float4* z0 = (const float4*)(z + (size_t)b0 * DD + zb_off);
    const float4* z1 = (const float4*)(z + (size_t)(b0 + 1) * DD + zb_off);
    const float4* x0 = (const float4*)(x + (size_t)b0 * DD);
    const float4* x1 = (const float4*)(x + (size_t)(b0 + 1) * DD);

    float a0[16], a1[16];
#pragma unroll
    for (int j = 0; j < 16; ++j) { a0[j] = 0.f; a1[j] = 0.f; }

#pragma unroll
    for (int t = 0; t < 10; ++t) {
        int k = lane * 4 + t * 128;
        if (k < 1176) {
            float4 v0 = (k < DHALF) ? z0[k >> 2] : x0[(k - DHALF) >> 2];
            float4 v1 = (k < DHALF) ? z1[k >> 2] : x1[(k - DHALF) >> 2];
#pragma unroll
            for (int j = 0; j < 16; ++j) {
                float4 wv = *(const float4*)(Ws + j * WPAD + k);
                a0[j] = fmaf(v0.x, wv.x, fmaf(v0.y, wv.y, fmaf(v0.z, wv.z, fmaf(v0.w, wv.w, a0[j]))));
                a1[j] = fmaf(v1.x, wv.x, fmaf(v1.y, wv.y, fmaf(v1.z, wv.z, fmaf(v1.w, wv.w, a1[j]))));
            }
        }
    }

    bool up16 = (lane & 16);
    float v[16];
#pragma unroll
    for (int j = 0; j < 16; ++j) {
        float send = up16 ? a0[j] : a1[j];
        float got = __shfl_xor_sync(0xffffffffu, send, 16);
        v[j] = (up16 ? a1[j] : a0[j]) + got;
    }
    // ownership tree: lane ends with its row's full sum for j = lane & 15
#pragma unroll
    for (int o = 8; o >= 1; o >>= 1) {
        bool up = (lane & o);
#pragma unroll
        for (int j = 0; j < o; ++j) {
            float keep = up ? v[j + o] : v[j];
            float send = up ? v[j] : v[j + o];
            v[j] = keep + __shfl_xor_sync(0xffffffffu, send, o);
        }
    }
    int j = lane & 15;
    float hv = v[0] + bis[j];
    float h = hv * frcp(1.f + fexpf_(-hv));

#pragma unroll
    for (int r = 0; r < RR; ++r) {
        float a = b1s[r * 16 + j];
#pragma unroll
        for (int k = 0; k < 16; ++k) {
            float hk = __shfl_sync(0xffffffffu, h, k, 16);
            a = fmaf(hk, W1s[(r * 16 + k) * 16 + j], a);
        }
        float tsw = a * frcp(1.f + fexpf_(-a));
        float a2 = b2s[r * 16 + j];
#pragma unroll
        for (int k = 0; k < 16; ++k) {
            float tk = __shfl_sync(0xffffffffu, tsw, k, 16);
            a2 = fmaf(tk, W2s[(r * 16 + k) * 16 + j], a2);
        }
        h += a2;
    }
    g_h[(size_t)(b0 + (lane >> 4)) * 16 + j] = h;
}

// ---------------------------------------------------------------------------
// fused W_out projection (f32x2) + fixed-count tanh-solver + accurate polish.
// Round-13 banked numerics; ONLY change: __launch_bounds__(128, 3) pins a
// 170-reg budget (vs natural ~150) to guarantee 3 CTAs = 12 warps/SM — the
// tanh pipe (rt 16, the binding resource) runs at only ~60% of its ceiling,
// and round-9 showed per-thread ILP can't fill it; more warps can.
// ---------------------------------------------------------------------------
__global__ void __launch_bounds__(128, 3) invert_k(float* __restrict__ z,
                                                   const float* __restrict__ Wout,
                                                   const float* __restrict__ bout,
                                                   int za_off) {
    __shared__ float Wt[16 * 8 * WTS];   // [k][ti][28] padded, conflict-free
    __shared__ float bos[192];
    __shared__ float hsh[BTILE * 17];
    __shared__ float red[BTILE * 8];

    int i0 = blockIdx.x * ITILE;
    int b0 = blockIdx.y * BTILE;

    for (int idx = threadIdx.x; idx < 16 * 192; idx += 128) {
        int k = idx / 192, c = idx - k * 192;
        int ti = c / 24, jj = c - ti * 24;
        Wt[(k * 8 + ti) * WTS + jj] = Wout[(size_t)k * 9408 + i0 * 24 + c];
    }
    for (int idx = threadIdx.x; idx < 192; idx += 128) bos[idx] = bout[i0 * 24 + idx];
    for (int idx = threadIdx.x; idx < BTILE * 16; idx += 128) {
        int tb = idx >> 4, k = idx & 15;
        hsh[tb * 17 + k] = g_h[(size_t)(b0 + tb) * 16 + k];
    }
    __syncthreads();

    int ti = threadIdx.x & 7, tb = threadIdx.x >> 3;
    int i = i0 + ti;

    // ---- joint projection for both elements (shared Wt reads) ----
    uint64_t pA[12], pB[12];
    {
        const uint64_t* bb = (const uint64_t*)(bos + ti * 24);
#pragma unroll
        for (int jj = 0; jj < 12; ++jj) { pA[jj] = bb[jj]; pB[jj] = bb[jj]; }
#pragma unroll
        for (int k = 0; k < 16; ++k) {
            float ha = hsh[tb * 17 + k];
            float hb = hsh[(tb + 16) * 17 + k];
            uint64_t h2a = pk2(ha, ha), h2b = pk2(hb, hb);
            const ulonglong2* wr = (const ulonglong2*)(Wt + (k * 8 + ti) * WTS);
#pragma unroll
            for (int c = 0; c < 6; ++c) {
                ulonglong2 wv = wr[c];
                pA[2 * c]     = ffma2_(h2a, wv.x, pA[2 * c]);
                pA[2 * c + 1] = ffma2_(h2a, wv.y, pA[2 * c + 1]);
                pB[2 * c]     = ffma2_(h2b, wv.x, pB[2 * c]);
                pB[2 * c + 1] = ffma2_(h2b, wv.y, pB[2 * c + 1]);
            }
        }
    }

#pragma unroll
    for (int e = 0; e < 2; ++e) {
        int b = b0 + tb + (e << 4);

        float p[24];
#pragma unroll
        for (int jj = 0; jj < 12; ++jj)
            upk2(p[2 * jj], p[2 * jj + 1], e ? pB[jj] : pA[jj]);

        float y = z[(size_t)b * DD + za_off + i];

        // unnormalized softmax weights
        float lm = p[0];
#pragma unroll
        for (int k = 1; k < 8; ++k) lm = fmaxf(lm, p[k]);
        float w[8];
        float wsum = 0.f;
#pragma unroll
        for (int k = 0; k < 8; ++k) { w[k] = fexpf_(p[k] - lm); wsum += w[k]; }
        float rw = frcp(wsum);

        // packed per-pair constants + bracket + weighted initial guess
        // (pairwise rcp: s0,s1 from one rcp of the product)
        uint64_t eh2[4], nmh2[4], w2p[4], we2[4];
        float sumwe = 0.f, cwsum = 0.f;
        float lo = 1e30f, hi = -1e30f;
#pragma unroll
        for (int q = 0; q < 4; ++q) {
            int k0 = 2 * q, k1 = 2 * q + 1;
            float mu0 = p[8 + k0], mu1 = p[8 + k1];
            float ls0 = p[16 + k0], ls1 = p[16 + k1];
            float e0 = fexpf_(-ls0), e1 = fexpf_(-ls1);
            float R = frcp(e0 * e1);
            float s0 = R * e1, s1 = R * e0;
            float h0 = 0.5f * e0, h1 = 0.5f * e1;
            eh2[q] = pk2(h0, h1);
            nmh2[q] = pk2(-mu0 * h0, -mu1 * h1);
            w2p[q] = pk2(w[k0], w[k1]);
            float we0 = w[k0] * h0, we1 = w[k1] * h1;
            we2[q] = pk2(we0, we1);
            sumwe += we0 + we1;
            float c0 = fmaf(y, s0, mu0), c1 = fmaf(y, s1, mu1);
            cwsum += w[k0] * c0 + w[k1] * c1;
            lo = fminf(lo, fminf(c0, c1));
            hi = fmaxf(hi, fmaxf(c0, c1));
        }
        lo -= 0.015625f;
        hi += 0.015625f;
        lo = fminf(fmaxf(lo, -100.f), 100.f);
        hi = fmaxf(fminf(hi, 100.f), lo);

        // accurate tanh(y/2)*Wsum target
        float tyW;
        {
            float ey = fexpf_(fminf(y, 80.f));
            tyW = (ey - 1.f) * frcp(ey + 1.f) * wsum;
        }
        float xv = fminf(fmaxf(cwsum * rw, lo), hi);

        // fixed-count safeguarded Newton on
        //   G(x) = sum w_k tanh((x-mu_k)/(2 s_k)) - tanh(y/2)*Wsum
#pragma unroll 1
        for (int it = 0; it < NSOLVE; ++it) {
            uint64_t xv2 = pk2(xv, xv);
            uint64_t S2 = 0ull, GB2 = 0ull;
#pragma unroll
            for (int q = 0; q < 4; ++q) {
                uint64_t a2 = ffma2_(xv2, eh2[q], nmh2[q]);
                float al, ah; upk2(al, ah, a2);
                uint64_t T2 = pk2(ftanh(al), ftanh(ah));
                S2 = ffma2_(w2p[q], T2, S2);
                GB2 = ffma2_(we2[q], fmul2_(T2, T2), GB2);
            }
            float sl, sh, gl, gh;
            upk2(sl, sh, S2); upk2(gl, gh, GB2);
            float S = (sl + sh) - tyW;
            float Gp = sumwe - (gl + gh);
            lo = (S < 0.f) ? xv : lo;
            hi = (S < 0.f) ? hi : xv;
            float xn = xv - S * frcp(Gp);
            float xm = 0.5f * (lo + hi);
            bool ok = (xn > lo) && (xn < hi);
            xv = ok ? xn : xm;
        }

        // accurate polish: eval1 = Newton; eval2 = Newton + logdet.
        // pairwise rcp on 1/(1+E); exp clamp 60 so pair products can't overflow.
        const float NC2 = -2.f * LOG2E_F;
        float ld = 0.f;
#pragma unroll 1
        for (int it = 0; it < 2; ++it) {
            float cdf = 0.f, sf = 0.f, pdf = 0.f;
#pragma unroll
            for (int q = 0; q < 4; ++q) {
                float h0, h1, nm0, nm1, w0, w1;
                upk2(h0, h1, eh2[q]);
                upk2(nm0, nm1, nmh2[q]);
                upk2(w0, w1, w2p[q]);
                float at0 = fmaf(xv, h0, nm0);
                float at1 = fmaf(xv, h1, nm1);
                float E0 = fexp2(fminf(at0 * NC2, 60.f));
                float E1 = fexp2(fminf(at1 * NC2, 60.f));
                float d0 = 1.f + E0, d1 = 1.f + E1;
                float R = frcp(d0 * d1);
                float r0 = R * d1, r1 = R * d0;
                float a0 = w0 * r0, t10 = a0 * E0;
                float a1 = w1 * r1, t11 = a1 * E1;
                cdf += a0 + a1;
                sf += t10 + t11;
                pdf = fmaf((t10 * r0) * 2.f, h0, fmaf((t11 * r1) * 2.f, h1, pdf));
            }
            float lc = flogf_(cdf), lsf = flogf_(sf);
            if (it == 1) ld = flogf_(pdf) - lc - lsf + flogf_(wsum);
            float f = lc - lsf - y;
            xv -= f * cdf * sf * frcp(pdf) * rw;
        }

        z[(size_t)b * DD + za_off + i] = xv;
        red[(tb + (e << 4)) * 8 + ti] = ld;
    }

    __syncthreads();
    if (threadIdx.x < BTILE) {
        const float* rr = red + threadIdx.x * 8;
        float s = rr[0] + rr[1] + rr[2] + rr[3] + rr[4] + rr[5] + rr[6] + rr[7];
        g_ldpart[(size_t)blockIdx.x * BB + b0 + threadIdx.x] += s;
    }
}

// ---------------------------------------------------------------------------
// finalize log_q (coalesced over transposed ldpart)
// ---------------------------------------------------------------------------
__global__ void __launch_bounds__(256) fin_k(float* __restrict__ lq) {
    int b = blockIdx.x * 256 + threadIdx.x;
    if (b < BB) {
        float s = lq[b];
#pragma unroll 1
        for (int j = 0; j < NBI; ++j) s += g_ldpart[(size_t)j * BB + b];
        lq[b] = s;
    }
}

extern "C" void kernel_launch(void* const* d_in, const int* in_sizes, int n_in,
                              void* d_out, int out_size) {
    (void)in_sizes; (void)n_in; (void)out_size;
    const float* x    = (const float*)d_in[0];
    const float* eps  = (const float*)d_in[1];
    const float* Win  = (const float*)d_in[2];
    const float* bin  = (const float*)d_in[3];
    const float* W1   = (const float*)d_in[4];
    const float* b1   = (const float*)d_in[5];
    const float* W2   = (const float*)d_in[6];
    const float* b2   = (const float*)d_in[7];
    const float* Wout = (const float*)d_in[8];
    const float* bout = (const float*)d_in[9];

    float* z = (float*)d_out;              // (B, D) working/output z
    float* lq = z + (size_t)BB * DD;       // (B,) log_q

    size_t smemA = (size_t)(16 * WPAD + 1024 + 1024 + 64 + 64 + 16) * sizeof(float);
    static int smem_set = 0;
    if (!smem_set) {
        cudaFuncSetAttribute((const void*)cond_k, cudaFuncAttributeMaxDynamicSharedMemorySize,
                             (int)smemA);
        smem_set = 1;
    }

    init_k<<<BB, 256>>>(eps, z, lq);

    for (int l = LL - 1; l >= 0; --l) {
        int za_off = (l & 1) ? DHALF : 0;
        int zb_off = (l & 1) ? 0 : DHALF;
        cond_k<<<BB / 32, CBLK, smemA>>>(z, x,
                                         Win + (size_t)l * 1176 * 16,
                                         bin + (size_t)l * 16,
                                         W1 + (size_t)l * RR * 256,
                                         b1 + (size_t)l * RR * 16,
                                         W2 + (size_t)l * RR * 256,
                                         b2 + (size_t)l * RR * 16,
                                         zb_off);
        invert_k<<<dim3(NBI, BB / BTILE), 128>>>(z,
                                                 Wout + (size_t)l * 16 * 9408,
                                                 bout + (size_t)l * 9408,
                                                 za_off);
    }

    fin_k<<<BB / 256, 256>>>(lq);
}

// round 16
// speedup vs baseline: 1.1425x; 1.0564x over previous
#include <cuda_runtime.h>
#include <cstdint>

#define BB 4096
#define DD 784
#define DHALF 392
#define HH 16
#define LL 4
#define RR 4
#define KK 8
#define ITILE 8
#define NBI 49      /* 392 / 8 */
#define BTILE 32    /* invert: rows per block (2 per thread) */
#define WPAD 1188   /* padded row length for transposed W_in in smem */
#define WTS 28      /* padded per-(k,ti) row stride in invert Wt tile */
#define NSOLVE 8    /* fixed solver iterations, no early exit */
#define CBLK 512    /* cond_k block size: 16 warps x 2 rows = 32 rows/block */
#define PBS 13      /* padded stride for the pB stash (2-way max conflicts) */
#define LOG2PI_F 1.8378770664093453f
#define LOG2E_F 1.4426950408889634f
#define LN2_F 0.6931471805599453f

// scratch (no allocations allowed)
__device__ float g_h[BB * HH];
__device__ float g_ldpart[NBI * BB];   // [j][b] transposed for coalesced access

__device__ __forceinline__ float frcp(float x) {
    float r; asm("rcp.approx.ftz.f32 %0, %1;" : "=f"(r) : "f"(x)); return r;
}
__device__ __forceinline__ float fexp2(float x) {
    float r; asm("ex2.approx.ftz.f32 %0, %1;" : "=f"(r) : "f"(x)); return r;
}
__device__ __forceinline__ float flog2(float x) {
    float r; asm("lg2.approx.ftz.f32 %0, %1;" : "=f"(r) : "f"(x)); return r;
}
__device__ __forceinline__ float ftanh(float x) {
    float r; asm("tanh.approx.f32 %0, %1;" : "=f"(r) : "f"(x)); return r;
}
__device__ __forceinline__ float fexpf_(float x) { return fexp2(x * LOG2E_F); }
__device__ __forceinline__ float flogf_(float x) { return flog2(x) * LN2_F; }

// packed fp32x2 helpers (sm_103a dual-fp32 pipe)
__device__ __forceinline__ uint64_t pk2(float lo, float hi) {
    uint64_t r; asm("mov.b64 %0, {%1, %2};" : "=l"(r) : "f"(lo), "f"(hi)); return r;
}
__device__ __forceinline__ void upk2(float& lo, float& hi, uint64_t v) {
    asm("mov.b64 {%0, %1}, %2;" : "=f"(lo), "=f"(hi) : "l"(v));
}
__device__ __forceinline__ uint64_t ffma2_(uint64_t a, uint64_t b, uint64_t c) {
    uint64_t d; asm("fma.rn.f32x2 %0, %1, %2, %3;" : "=l"(d) : "l"(a), "l"(b), "l"(c)); return d;
}
__device__ __forceinline__ uint64_t fmul2_(uint64_t a, uint64_t b) {
    uint64_t d; asm("mul.rn.f32x2 %0, %1, %2;" : "=l"(d) : "l"(a), "l"(b)); return d;
}

// ---------------------------------------------------------------------------
// init (float4-vectorized copy + squared-sum)
// ---------------------------------------------------------------------------
__global__ void __launch_bounds__(256) init_k(const float* __restrict__ eps,
                                              float* __restrict__ z,
                                              float* __restrict__ lq) {
    int b = blockIdx.x;
    const float4* e4 = (const float4*)(eps + (size_t)b * DD);
    float4* z4 = (float4*)(z + (size_t)b * DD);
    float s = 0.f;
    if (threadIdx.x < 196) {
        float4 v = e4[threadIdx.x];
        z4[threadIdx.x] = v;
        s = v.x * v.x + v.y * v.y + v.z * v.z + v.w * v.w;
    }
    __shared__ float red[256];
    red[threadIdx.x] = s;
    __syncthreads();
    for (int o = 128; o > 0; o >>= 1) {
        if (threadIdx.x < o) red[threadIdx.x] += red[threadIdx.x + o];
        __syncthreads();
    }
    if (threadIdx.x == 0) lq[b] = -0.5f * (red[0] + (float)DD * LOG2PI_F);
    if (threadIdx.x < NBI) g_ldpart[(size_t)threadIdx.x * BB + b] = 0.f;
}

// ---------------------------------------------------------------------------
// conditioner: 512 threads (16 warps x 2 rows = 32 rows/block), grid 128.
// ---------------------------------------------------------------------------
__global__ void __launch_bounds__(CBLK) cond_k(const float* __restrict__ z,
                                               const float* __restrict__ x,
                                               const float* __restrict__ Win,
                                               const float* __restrict__ bin,
                                               const float* __restrict__ W1,
                                               const float* __restrict__ b1v,
                                               const float* __restrict__ W2,
                                               const float* __restrict__ b2v,
                                               int zb_off) {
    extern __shared__ float sm[];
    float* Ws = sm;                       // 16 * WPAD (transposed)
    float* W1s = Ws + 16 * WPAD;          // 1024
    float* W2s = W1s + 1024;              // 1024
    float* b1s = W2s + 1024;              // 64
    float* b2s = b1s + 64;                // 64
    float* bis = b2s + 64;                // 16

    for (int idx = threadIdx.x; idx < 1176 * 16; idx += CBLK) {
        int k = idx >> 4, j = idx & 15;
        Ws[j * WPAD + k] = Win[idx];
    }
    for (int idx = threadIdx.x; idx < 16 * (WPAD - 1176); idx += CBLK) {
        int j = idx / (WPAD - 1176), c = idx % (WPAD - 1176);
        Ws[j * WPAD + 1176 + c] = 0.f;
    }
    for (int i = threadIdx.x; i < 1024; i += CBLK) { W1s[i] = W1[i]; W2s[i] = W2[i]; }
    if (threadIdx.x < 64) { b1s[threadIdx.x] = b1v[threadIdx.x]; b2s[threadIdx.x] = b2v[threadIdx.x]; }
    else if (threadIdx.x >= 64 && threadIdx.x < 80) bis[threadIdx.x - 64] = bin[threadIdx.x - 64];
    __syncthreads();

    int warp = threadIdx.x >> 5, lane = threadIdx.x & 31;
    int b0 = blockIdx.x * 32 + warp * 2;
    const float4* z0 = (const float4*)(z + (size_t)b0 * DD + zb_off);
    const float4* z1 = (const float4*)(z + (size_t)(b0 + 1) * DD + zb_off);
    const float4* x0 = (const float4*)(x + (size_t)b0 * DD);
    const float4* x1 = (const float4*)(x + (size_t)(b0 + 1) * DD);

    float a0[16], a1[16];
#pragma unroll
    for (int j = 0; j < 16; ++j) { a0[j] = 0.f; a1[j] = 0.f; }

#pragma unroll
    for (int t = 0; t < 10; ++t) {
        int k = lane * 4 + t * 128;
        if (k < 1176) {
            float4 v0 = (k < DHALF) ? z0[k >> 2] : x0[(k - DHALF) >> 2];
            float4 v1 = (k < DHALF) ? z1[k >> 2] : x1[(k - DHALF) >> 2];
#pragma unroll
            for (int j = 0; j < 16; ++j) {
                float4 wv = *(const float4*)(Ws + j * WPAD + k);
                a0[j] = fmaf(v0.x, wv.x, fmaf(v0.y, wv.y, fmaf(v0.z, wv.z, fmaf(v0.w, wv.w, a0[j]))));
                a1[j] = fmaf(v1.x, wv.x, fmaf(v1.y, wv.y, fmaf(v1.z, wv.z, fmaf(v1.w, wv.w, a1[j]))));
            }
        }
    }

    bool up16 = (lane & 16);
    float v[16];
#pragma unroll
    for (int j = 0; j < 16; ++j) {
        float send = up16 ? a0[j] : a1[j];
        float got = __shfl_xor_sync(0xffffffffu, send, 16);
        v[j] = (up16 ? a1[j] : a0[j]) + got;
    }
    // ownership tree: lane ends with its row's full sum for j = lane & 15
#pragma unroll
    for (int o = 8; o >= 1; o >>= 1) {
        bool up = (lane & o);
#pragma unroll
        for (int j = 0; j < o; ++j) {
            float keep = up ? v[j + o] : v[j];
            float send = up ? v[j] : v[j + o];
            v[j] = keep + __shfl_xor_sync(0xffffffffu, send, o);
        }
    }
    int j = lane & 15;
    float hv = v[0] + bis[j];
    float h = hv * frcp(1.f + fexpf_(-hv));

#pragma unroll
    for (int r = 0; r < RR; ++r) {
        float a = b1s[r * 16 + j];
#pragma unroll
        for (int k = 0; k < 16; ++k) {
            float hk = __shfl_sync(0xffffffffu, h, k, 16);
            a = fmaf(hk, W1s[(r * 16 + k) * 16 + j], a);
        }
        float tsw = a * frcp(1.f + fexpf_(-a));
        float a2 = b2s[r * 16 + j];
#pragma unroll
        for (int k = 0; k < 16; ++k) {
            float tk = __shfl_sync(0xffffffffu, tsw, k, 16);
            a2 = fmaf(tk, W2s[(r * 16 + k) * 16 + j], a2);
        }
        h += a2;
    }
    g_h[(size_t)(b0 + (lane >> 4)) * 16 + j] = h;
}

// ---------------------------------------------------------------------------
// fused W_out projection (f32x2) + fixed-count tanh-solver + accurate polish.
// Round-13 numerics. Register-pressure fix: pB (element B's projection, 24
// regs) no longer stays live through element A's solve — it is stashed in
// shared memory right after the joint projection and reloaded when element B
// starts. Peak live registers drop to ~150, so __launch_bounds__(128, 3)
// (170-reg budget) now yields 3 CTAs = 12 warps/SM WITHOUT spills, covering
// the half-rate tanh pipe that binds this kernel.
// ---------------------------------------------------------------------------
__global__ void __launch_bounds__(128, 3) invert_k(float* __restrict__ z,
                                                   const float* __restrict__ Wout,
                                                   const float* __restrict__ bout,
                                                   int za_off) {
    __shared__ float Wt[16 * 8 * WTS];   // [k][ti][28] padded, conflict-free
    __shared__ float bos[192];
    __shared__ float hsh[BTILE * 17];
    __shared__ float red[BTILE * 8];
    __shared__ uint64_t pBs[128 * PBS]; // stash for element B's projection

    int i0 = blockIdx.x * ITILE;
    int b0 = blockIdx.y * BTILE;

    for (int idx = threadIdx.x; idx < 16 * 192; idx += 128) {
        int k = idx / 192, c = idx - k * 192;
        int ti = c / 24, jj = c - ti * 24;
        Wt[(k * 8 + ti) * WTS + jj] = Wout[(size_t)k * 9408 + i0 * 24 + c];
    }
    for (int idx = threadIdx.x; idx < 192; idx += 128) bos[idx] = bout[i0 * 24 + idx];
    for (int idx = threadIdx.x; idx < BTILE * 16; idx += 128) {
        int tb = idx >> 4, k = idx & 15;
        hsh[tb * 17 + k] = g_h[(size_t)(b0 + tb) * 16 + k];
    }
    __syncthreads();

    int ti = threadIdx.x & 7, tb = threadIdx.x >> 3;
    int i = i0 + ti;

    // ---- joint projection for both elements (shared Wt reads); element B's
    //      result goes straight to the smem stash so its 24 regs die here ----
    uint64_t pA[12];
    {
        uint64_t pB[12];
        const uint64_t* bb = (const uint64_t*)(bos + ti * 24);
#pragma unroll
        for (int jj = 0; jj < 12; ++jj) { pA[jj] = bb[jj]; pB[jj] = bb[jj]; }
#pragma unroll
        for (int k = 0; k < 16; ++k) {
            float ha = hsh[tb * 17 + k];
            float hb = hsh[(tb + 16) * 17 + k];
            uint64_t h2a = pk2(ha, ha), h2b = pk2(hb, hb);
            const ulonglong2* wr = (const ulonglong2*)(Wt + (k * 8 + ti) * WTS);
#pragma unroll
            for (int c = 0; c < 6; ++c) {
                ulonglong2 wv = wr[c];
                pA[2 * c]     = ffma2_(h2a, wv.x, pA[2 * c]);
                pA[2 * c + 1] = ffma2_(h2a, wv.y, pA[2 * c + 1]);
                pB[2 * c]     = ffma2_(h2b, wv.x, pB[2 * c]);
                pB[2 * c + 1] = ffma2_(h2b, wv.y, pB[2 * c + 1]);
            }
        }
#pragma unroll
        for (int jj = 0; jj < 12; ++jj) pBs[threadIdx.x * PBS + jj] = pB[jj];
    }

#pragma unroll 1
    for (int e = 0; e < 2; ++e) {
        int b = b0 + tb + (e << 4);

        float p[24];
        if (e == 0) {
#pragma unroll
            for (int jj = 0; jj < 12; ++jj) upk2(p[2 * jj], p[2 * jj + 1], pA[jj]);
        } else {
#pragma unroll
            for (int jj = 0; jj < 12; ++jj)
                upk2(p[2 * jj], p[2 * jj + 1], pBs[threadIdx.x * PBS + jj]);
        }

        float y = z[(size_t)b * DD + za_off + i];

        // unnormalized softmax weights
        float lm = p[0];
#pragma unroll
        for (int k = 1; k < 8; ++k) lm = fmaxf(lm, p[k]);
        float w[8];
        float wsum = 0.f;
#pragma unroll
        for (int k = 0; k < 8; ++k) { w[k] = fexpf_(p[k] - lm); wsum += w[k]; }
        float rw = frcp(wsum);

        // packed per-pair constants + bracket + weighted initial guess
        // (pairwise rcp: s0,s1 from one rcp of the product)
        uint64_t eh2[4], nmh2[4], w2p[4], we2[4];
        float sumwe = 0.f, cwsum = 0.f;
        float lo = 1e30f, hi = -1e30f;
#pragma unroll
        for (int q = 0; q < 4; ++q) {
            int k0 = 2 * q, k1 = 2 * q + 1;
            float mu0 = p[8 + k0], mu1 = p[8 + k1];
            float ls0 = p[16 + k0], ls1 = p[16 + k1];
            float e0 = fexpf_(-ls0), e1 = fexpf_(-ls1);
            float R = frcp(e0 * e1);
            float s0 = R * e1, s1 = R * e0;
            float h0 = 0.5f * e0, h1 = 0.5f * e1;
            eh2[q] = pk2(h0, h1);
            nmh2[q] = pk2(-mu0 * h0, -mu1 * h1);
            w2p[q] = pk2(w[k0], w[k1]);
            float we0 = w[k0] * h0, we1 = w[k1] * h1;
            we2[q] = pk2(we0, we1);
            sumwe += we0 + we1;
            float c0 = fmaf(y, s0, mu0), c1 = fmaf(y, s1, mu1);
            cwsum += w[k0] * c0 + w[k1] * c1;
            lo = fminf(lo, fminf(c0, c1));
            hi = fmaxf(hi, fmaxf(c0, c1));
        }
        lo -= 0.015625f;
        hi += 0.015625f;
        lo = fminf(fmaxf(lo, -100.f), 100.f);
        hi = fmaxf(fminf(hi, 100.f), lo);

        // accurate tanh(y/2)*Wsum target
        float tyW;
        {
            float ey = fexpf_(fminf(y, 80.f));
            tyW = (ey - 1.f) * frcp(ey + 1.f) * wsum;
        }
        float xv = fminf(fmaxf(cwsum * rw, lo), hi);

        // fixed-count safeguarded Newton on
        //   G(x) = sum w_k tanh((x-mu_k)/(2 s_k)) - tanh(y/2)*Wsum
#pragma unroll 1
        for (int it = 0; it < NSOLVE; ++it) {
            uint64_t xv2 = pk2(xv, xv);
            uint64_t S2 = 0ull, GB2 = 0ull;
#pragma unroll
            for (int q = 0; q < 4; ++q) {
                uint64_t a2 = ffma2_(xv2, eh2[q], nmh2[q]);
                float al, ah; upk2(al, ah, a2);
                uint64_t T2 = pk2(ftanh(al), ftanh(ah));
                S2 = ffma2_(w2p[q], T2, S2);
                GB2 = ffma2_(we2[q], fmul2_(T2, T2), GB2);
            }
            float sl, sh, gl, gh;
            upk2(sl, sh, S2); upk2(gl, gh, GB2);
            float S = (sl + sh) - tyW;
            float Gp = sumwe - (gl + gh);
            lo = (S < 0.f) ? xv : lo;
            hi = (S < 0.f) ? hi : xv;
            float xn = xv - S * frcp(Gp);
            float xm = 0.5f * (lo + hi);
            bool ok = (xn > lo) && (xn < hi);
            xv = ok ? xn : xm;
        }

        // accurate polish: eval1 = Newton; eval2 = Newton + logdet.
        // pairwise rcp on 1/(1+E); exp clamp 60 so pair products can't overflow.
        const float NC2 = -2.f * LOG2E_F;
        float ld = 0.f;
#pragma unroll 1
        for (int it = 0; it < 2; ++it) {
            float cdf = 0.f, sf = 0.f, pdf = 0.f;
#pragma unroll
            for (int q = 0; q < 4; ++q) {
                float h0, h1, nm0, nm1, w0, w1;
                upk2(h0, h1, eh2[q]);
                upk2(nm0, nm1, nmh2[q]);
                upk2(w0, w1, w2p[q]);
                float at0 = fmaf(xv, h0, nm0);
                float at1 = fmaf(xv, h1, nm1);
                float E0 = fexp2(fminf(at0 * NC2, 60.f));
                float E1 = fexp2(fminf(at1 * NC2, 60.f));
                float d0 = 1.f + E0, d1 = 1.f + E1;
                float R = frcp(d0 * d1);
                float r0 = R * d1, r1 = R * d0;
                float a0 = w0 * r0, t10 = a0 * E0;
                float a1 = w1 * r1, t11 = a1 * E1;
                cdf += a0 + a1;
                sf += t10 + t11;
                pdf = fmaf((t10 * r0) * 2.f, h0, fmaf((t11 * r1) * 2.f, h1, pdf));
            }
            float lc = flogf_(cdf), lsf = flogf_(sf);
            if (it == 1) ld = flogf_(pdf) - lc - lsf + flogf_(wsum);
            float f = lc - lsf - y;
            xv -= f * cdf * sf * frcp(pdf) * rw;
        }

        z[(size_t)b * DD + za_off + i] = xv;
        red[(tb + (e << 4)) * 8 + ti] = ld;
    }

    __syncthreads();
    if (threadIdx.x < BTILE) {
        const float* rr = red + threadIdx.x * 8;
        float s = rr[0] + rr[1] + rr[2] + rr[3] + rr[4] + rr[5] + rr[6] + rr[7];
        g_ldpart[(size_t)blockIdx.x * BB + b0 + threadIdx.x] += s;
    }
}

// ---------------------------------------------------------------------------
// finalize log_q (coalesced over transposed ldpart)
// ---------------------------------------------------------------------------
__global__ void __launch_bounds__(256) fin_k(float* __restrict__ lq) {
    int b = blockIdx.x * 256 + threadIdx.x;
    if (b < BB) {
        float s = lq[b];
#pragma unroll 1
        for (int j = 0; j < NBI; ++j) s += g_ldpart[(size_t)j * BB + b];
        lq[b] = s;
    }
}

extern "C" void kernel_launch(void* const* d_in, const int* in_sizes, int n_in,
                              void* d_out, int out_size) {
    (void)in_sizes; (void)n_in; (void)out_size;
    const float* x    = (const float*)d_in[0];
    const float* eps  = (const float*)d_in[1];
    const float* Win  = (const float*)d_in[2];
    const float* bin  = (const float*)d_in[3];
    const float* W1   = (const float*)d_in[4];
    const float* b1   = (const float*)d_in[5];
    const float* W2   = (const float*)d_in[6];
    const float* b2   = (const float*)d_in[7];
    const float* Wout = (const float*)d_in[8];
    const float* bout = (const float*)d_in[9];

    float* z = (float*)d_out;              // (B, D) working/output z
    float* lq = z + (size_t)BB * DD;       // (B,) log_q

    size_t smemA = (size_t)(16 * WPAD + 1024 + 1024 + 64 + 64 + 16) * sizeof(float);
    static int smem_set = 0;
    if (!smem_set) {
        cudaFuncSetAttribute((const void*)cond_k, cudaFuncAttributeMaxDynamicSharedMemorySize,
                             (int)smemA);
        smem_set = 1;
    }

    init_k<<<BB, 256>>>(eps, z, lq);

    for (int l = LL - 1; l >= 0; --l) {
        int za_off = (l & 1) ? DHALF : 0;
        int zb_off = (l & 1) ? 0 : DHALF;
        cond_k<<<BB / 32, CBLK, smemA>>>(z, x,
                                         Win + (size_t)l * 1176 * 16,
                                         bin + (size_t)l * 16,
                                         W1 + (size_t)l * RR * 256,
                                         b1 + (size_t)l * RR * 16,
                                         W2 + (size_t)l * RR * 256,
                                         b2 + (size_t)l * RR * 16,
                                         zb_off);
        invert_k<<<dim3(NBI, BB / BTILE), 128>>>(z,
                                                 Wout + (size_t)l * 16 * 9408,
                                                 bout + (size_t)l * 9408,
                                                 za_off);
    }

    fin_k<<<BB / 256, 256>>>(lq);
}

// round 17
// speedup vs baseline: 1.1467x; 1.0037x over previous
#include <cuda_runtime.h>
#include <cstdint>

#define BB 4096
#define DD 784
#define DHALF 392
#define HH 16
#define LL 4
#define RR 4
#define KK 8
#define ITILE 8
#define NBI 49      /* 392 / 8 */
#define BTILE 32    /* invert: rows per block (2 per thread) */
#define WPAD 1188   /* padded row length for transposed W_in in smem */
#define WTS 28      /* padded per-(k,ti) row stride in invert Wt tile */
#define NSOLVE 8    /* fixed solver iterations, no early exit */
#define CBLK 512    /* cond_k block size: 16 warps x 2 rows = 32 rows/block */
#define PBS 13      /* padded stride for the pB stash (2-way max conflicts) */
#define LOG2PI_F 1.8378770664093453f
#define LOG2E_F 1.4426950408889634f
#define LN2_F 0.6931471805599453f

// scratch (no allocations allowed)
__device__ float g_h[BB * HH];
__device__ float g_ldpart[NBI * BB];   // [j][b] transposed for coalesced access

__device__ __forceinline__ float frcp(float x) {
    float r; asm("rcp.approx.ftz.f32 %0, %1;" : "=f"(r) : "f"(x)); return r;
}
__device__ __forceinline__ float fexp2(float x) {
    float r; asm("ex2.approx.ftz.f32 %0, %1;" : "=f"(r) : "f"(x)); return r;
}
__device__ __forceinline__ float flog2(float x) {
    float r; asm("lg2.approx.ftz.f32 %0, %1;" : "=f"(r) : "f"(x)); return r;
}
__device__ __forceinline__ float ftanh(float x) {
    float r; asm("tanh.approx.f32 %0, %1;" : "=f"(r) : "f"(x)); return r;
}
__device__ __forceinline__ float fexpf_(float x) { return fexp2(x * LOG2E_F); }
__device__ __forceinline__ float flogf_(float x) { return flog2(x) * LN2_F; }

// packed fp32x2 helpers (sm_103a dual-fp32 pipe)
__device__ __forceinline__ uint64_t pk2(float lo, float hi) {
    uint64_t r; asm("mov.b64 %0, {%1, %2};" : "=l"(r) : "f"(lo), "f"(hi)); return r;
}
__device__ __forceinline__ void upk2(float& lo, float& hi, uint64_t v) {
    asm("mov.b64 {%0, %1}, %2;" : "=f"(lo), "=f"(hi) : "l"(v));
}
__device__ __forceinline__ uint64_t ffma2_(uint64_t a, uint64_t b, uint64_t c) {
    uint64_t d; asm("fma.rn.f32x2 %0, %1, %2, %3;" : "=l"(d) : "l"(a), "l"(b), "l"(c)); return d;
}
__device__ __forceinline__ uint64_t fmul2_(uint64_t a, uint64_t b) {
    uint64_t d; asm("mul.rn.f32x2 %0, %1, %2;" : "=l"(d) : "l"(a), "l"(b)); return d;
}

// ---------------------------------------------------------------------------
// init (float4-vectorized copy + squared-sum)
// ---------------------------------------------------------------------------
__global__ void __launch_bounds__(256) init_k(const float* __restrict__ eps,
                                              float* __restrict__ z,
                                              float* __restrict__ lq) {
    int b = blockIdx.x;
    const float4* e4 = (const float4*)(eps + (size_t)b * DD);
    float4* z4 = (float4*)(z + (size_t)b * DD);
    float s = 0.f;
    if (threadIdx.x < 196) {
        float4 v = e4[threadIdx.x];
        z4[threadIdx.x] = v;
        s = v.x * v.x + v.y * v.y + v.z * v.z + v.w * v.w;
    }
    __shared__ float red[256];
    red[threadIdx.x] = s;
    __syncthreads();
    for (int o = 128; o > 0; o >>= 1) {
        if (threadIdx.x < o) red[threadIdx.x] += red[threadIdx.x + o];
        __syncthreads();
    }
    if (threadIdx.x == 0) lq[b] = -0.5f * (red[0] + (float)DD * LOG2PI_F);
    if (threadIdx.x < NBI) g_ldpart[(size_t)threadIdx.x * BB + b] = 0.f;
}

// ---------------------------------------------------------------------------
// conditioner: 512 threads (16 warps x 2 rows = 32 rows/block), grid 128.
// W_in staged via float4 loads (rows are 16 floats = 4 quads) -> 4x fewer
// LDG, front-batched for the L1tex queue; transposed scalar STS unchanged.
// ---------------------------------------------------------------------------
__global__ void __launch_bounds__(CBLK) cond_k(const float* __restrict__ z,
                                               const float* __restrict__ x,
                                               const float* __restrict__ Win,
                                               const float* __restrict__ bin,
                                               const float* __restrict__ W1,
                                               const float* __restrict__ b1v,
                                               const float* __restrict__ W2,
                                               const float* __restrict__ b2v,
                                               int zb_off) {
    extern __shared__ float sm[];
    float* Ws = sm;                       // 16 * WPAD (transposed)
    float* W1s = Ws + 16 * WPAD;          // 1024
    float* W2s = W1s + 1024;              // 1024
    float* b1s = W2s + 1024;              // 64
    float* b2s = b1s + 64;                // 64
    float* bis = b2s + 64;                // 16

    {
        const float4* W4 = (const float4*)Win;   // [1176][4] float4
        for (int idx = threadIdx.x; idx < 1176 * 4; idx += CBLK) {
            int k = idx >> 2, jq = idx & 3;
            float4 v = W4[idx];
            float* dst = Ws + (jq * 4) * WPAD + k;
            dst[0] = v.x;
            dst[WPAD] = v.y;
            dst[2 * WPAD] = v.z;
            dst[3 * WPAD] = v.w;
        }
    }
    for (int idx = threadIdx.x; idx < 16 * (WPAD - 1176); idx += CBLK) {
        int j = idx / (WPAD - 1176), c = idx % (WPAD - 1176);
        Ws[j * WPAD + 1176 + c] = 0.f;
    }
    for (int i = threadIdx.x; i < 1024; i += CBLK) { W1s[i] = W1[i]; W2s[i] = W2[i]; }
    if (threadIdx.x < 64) { b1s[threadIdx.x] = b1v[threadIdx.x]; b2s[threadIdx.x] = b2v[threadIdx.x]; }
    else if (threadIdx.x >= 64 && threadIdx.x < 80) bis[threadIdx.x - 64] = bin[threadIdx.x - 64];
    __syncthreads();

    int warp = threadIdx.x >> 5, lane = threadIdx.x & 31;
    int b0 = blockIdx.x * 32 + warp * 2;
    const float4* z0 = (const float4*)(z + (size_t)b0 * DD + zb_off);
    const float4* z1 = (const float4*)(z + (size_t)(b0 + 1) * DD + zb_off);
    const float4* x0 = (const float4*)(x + (size_t)b0 * DD);
    const float4* x1 = (const float4*)(x + (size_t)(b0 + 1) * DD);

    float a0[16], a1[16];
#pragma unroll
    for (int j = 0; j < 16; ++j) { a0[j] = 0.f; a1[j] = 0.f; }

#pragma unroll
    for (int t = 0; t < 10; ++t) {
        int k = lane * 4 + t * 128;
        if (k < 1176) {
            float4 v0 = (k < DHALF) ? z0[k >> 2] : x0[(k - DHALF) >> 2];
            float4 v1 = (k < DHALF) ? z1[k >> 2] : x1[(k - DHALF) >> 2];
#pragma unroll
            for (int j = 0; j < 16; ++j) {
                float4 wv = *(const float4*)(Ws + j * WPAD + k);
                a0[j] = fmaf(v0.x, wv.x, fmaf(v0.y, wv.y, fmaf(v0.z, wv.z, fmaf(v0.w, wv.w, a0[j]))));
                a1[j] = fmaf(v1.x, wv.x, fmaf(v1.y, wv.y, fmaf(v1.z, wv.z, fmaf(v1.w, wv.w, a1[j]))));
            }
        }
    }

    bool up16 = (lane & 16);
    float v[16];
#pragma unroll
    for (int j = 0; j < 16; ++j) {
        float send = up16 ? a0[j] : a1[j];
        float got = __shfl_xor_sync(0xffffffffu, send, 16);
        v[j] = (up16 ? a1[j] : a0[j]) + got;
    }
    // ownership tree: lane ends with its row's full sum for j = lane & 15
#pragma unroll
    for (int o = 8; o >= 1; o >>= 1) {
        bool up = (lane & o);
#pragma unroll
        for (int j = 0; j < o; ++j) {
            float keep = up ? v[j + o] : v[j];
            float send = up ? v[j] : v[j + o];
            v[j] = keep + __shfl_xor_sync(0xffffffffu, send, o);
        }
    }
    int j = lane & 15;
    float hv = v[0] + bis[j];
    float h = hv * frcp(1.f + fexpf_(-hv));

#pragma unroll
    for (int r = 0; r < RR; ++r) {
        float a = b1s[r * 16 + j];
#pragma unroll
        for (int k = 0; k < 16; ++k) {
            float hk = __shfl_sync(0xffffffffu, h, k, 16);
            a = fmaf(hk, W1s[(r * 16 + k) * 16 + j], a);
        }
        float tsw = a * frcp(1.f + fexpf_(-a));
        float a2 = b2s[r * 16 + j];
#pragma unroll
        for (int k = 0; k < 16; ++k) {
            float tk = __shfl_sync(0xffffffffu, tsw, k, 16);
            a2 = fmaf(tk, W2s[(r * 16 + k) * 16 + j], a2);
        }
        h += a2;
    }
    g_h[(size_t)(b0 + (lane >> 4)) * 16 + j] = h;
}

// ---------------------------------------------------------------------------
// fused W_out projection (f32x2) + fixed-count tanh-solver + accurate polish.
// Round-16 banked configuration: pB stashed in smem after the joint
// projection (peak live regs ~150), __launch_bounds__(128, 3) -> 3 CTAs =
// 12 warps/SM without spills. invert_k is ~95% MUFU-pipe saturated; no
// further changes here.
// ---------------------------------------------------------------------------
__global__ void __launch_bounds__(128, 3) invert_k(float* __restrict__ z,
                                                   const float* __restrict__ Wout,
                                                   const float* __restrict__ bout,
                                                   int za_off) {
    __shared__ float Wt[16 * 8 * WTS];   // [k][ti][28] padded, conflict-free
    __shared__ float bos[192];
    __shared__ float hsh[BTILE * 17];
    __shared__ float red[BTILE * 8];
    __shared__ uint64_t pBs[128 * PBS]; // stash for element B's projection

    int i0 = blockIdx.x * ITILE;
    int b0 = blockIdx.y * BTILE;

    for (int idx = threadIdx.x; idx < 16 * 192; idx += 128) {
        int k = idx / 192, c = idx - k * 192;
        int ti = c / 24, jj = c - ti * 24;
        Wt[(k * 8 + ti) * WTS + jj] = Wout[(size_t)k * 9408 + i0 * 24 + c];
    }
    for (int idx = threadIdx.x; idx < 192; idx += 128) bos[idx] = bout[i0 * 24 + idx];
    for (int idx = threadIdx.x; idx < BTILE * 16; idx += 128) {
        int tb = idx >> 4, k = idx & 15;
        hsh[tb * 17 + k] = g_h[(size_t)(b0 + tb) * 16 + k];
    }
    __syncthreads();

    int ti = threadIdx.x & 7, tb = threadIdx.x >> 3;
    int i = i0 + ti;

    // ---- joint projection for both elements (shared Wt reads); element B's
    //      result goes straight to the smem stash so its 24 regs die here ----
    uint64_t pA[12];
    {
        uint64_t pB[12];
        const uint64_t* bb = (const uint64_t*)(bos + ti * 24);
#pragma unroll
        for (int jj = 0; jj < 12; ++jj) { pA[jj] = bb[jj]; pB[jj] = bb[jj]; }
#pragma unroll
        for (int k = 0; k < 16; ++k) {
            float ha = hsh[tb * 17 + k];
            float hb = hsh[(tb + 16) * 17 + k];
            uint64_t h2a = pk2(ha, ha), h2b = pk2(hb, hb);
            const ulonglong2* wr = (const ulonglong2*)(Wt + (k * 8 + ti) * WTS);
#pragma unroll
            for (int c = 0; c < 6; ++c) {
                ulonglong2 wv = wr[c];
                pA[2 * c]     = ffma2_(h2a, wv.x, pA[2 * c]);
                pA[2 * c + 1] = ffma2_(h2a, wv.y, pA[2 * c + 1]);
                pB[2 * c]     = ffma2_(h2b, wv.x, pB[2 * c]);
                pB[2 * c + 1] = ffma2_(h2b, wv.y, pB[2 * c + 1]);
            }
        }
#pragma unroll
        for (int jj = 0; jj < 12; ++jj) pBs[threadIdx.x * PBS + jj] = pB[jj];
    }

#pragma unroll 1
    for (int e = 0; e < 2; ++e) {
        int b = b0 + tb + (e << 4);

        float p[24];
        if (e == 0) {
#pragma unroll
            for (int jj = 0; jj < 12; ++jj) upk2(p[2 * jj], p[2 * jj + 1], pA[jj]);
        } else {
#pragma unroll
            for (int jj = 0; jj < 12; ++jj)
                upk2(p[2 * jj], p[2 * jj + 1], pBs[threadIdx.x * PBS + jj]);
        }

        float y = z[(size_t)b * DD + za_off + i];

        // unnormalized softmax weights
        float lm = p[0];
#pragma unroll
        for (int k = 1; k < 8; ++k) lm = fmaxf(lm, p[k]);
        float w[8];
        float wsum = 0.f;
#pragma unroll
        for (int k = 0; k < 8; ++k) { w[k] = fexpf_(p[k] - lm); wsum += w[k]; }
        float rw = frcp(wsum);

        // packed per-pair constants + bracket + weighted initial guess
        // (pairwise rcp: s0,s1 from one rcp of the product)
        uint64_t eh2[4], nmh2[4], w2p[4], we2[4];
        float sumwe = 0.f, cwsum = 0.f;
        float lo = 1e30f, hi = -1e30f;
#pragma unroll
        for (int q = 0; q < 4; ++q) {
            int k0 = 2 * q, k1 = 2 * q + 1;
            float mu0 = p[8 + k0], mu1 = p[8 + k1];
            float ls0 = p[16 + k0], ls1 = p[16 + k1];
            float e0 = fexpf_(-ls0), e1 = fexpf_(-ls1);
            float R = frcp(e0 * e1);
            float s0 = R * e1, s1 = R * e0;
            float h0 = 0.5f * e0, h1 = 0.5f * e1;
            eh2[q] = pk2(h0, h1);
            nmh2[q] = pk2(-mu0 * h0, -mu1 * h1);
            w2p[q] = pk2(w[k0], w[k1]);
            float we0 = w[k0] * h0, we1 = w[k1] * h1;
            we2[q] = pk2(we0, we1);
            sumwe += we0 + we1;
            float c0 = fmaf(y, s0, mu0), c1 = fmaf(y, s1, mu1);
            cwsum += w[k0] * c0 + w[k1] * c1;
            lo = fminf(lo, fminf(c0, c1));
            hi = fmaxf(hi, fmaxf(c0, c1));
        }
        lo -= 0.015625f;
        hi += 0.015625f;
        lo = fminf(fmaxf(lo, -100.f), 100.f);
        hi = fmaxf(fminf(hi, 100.f), lo);

        // accurate tanh(y/2)*Wsum target
        float tyW;
        {
            float ey = fexpf_(fminf(y, 80.f));
            tyW = (ey - 1.f) * frcp(ey + 1.f) * wsum;
        }
        float xv = fminf(fmaxf(cwsum * rw, lo), hi);

        // fixed-count safeguarded Newton on
        //   G(x) = sum w_k tanh((x-mu_k)/(2 s_k)) - tanh(y/2)*Wsum
#pragma unroll 1
        for (int it = 0; it < NSOLVE; ++it) {
            uint64_t xv2 = pk2(xv, xv);
            uint64_t S2 = 0ull, GB2 = 0ull;
#pragma unroll
            for (int q = 0; q < 4; ++q) {
                uint64_t a2 = ffma2_(xv2, eh2[q], nmh2[q]);
                float al, ah; upk2(al, ah, a2);
                uint64_t T2 = pk2(ftanh(al), ftanh(ah));
                S2 = ffma2_(w2p[q], T2, S2);
                GB2 = ffma2_(we2[q], fmul2_(T2, T2), GB2);
            }
            float sl, sh, gl, gh;
            upk2(sl, sh, S2); upk2(gl, gh, GB2);
            float S = (sl + sh) - tyW;
            float Gp = sumwe - (gl + gh);
            lo = (S < 0.f) ? xv : lo;
            hi = (S < 0.f) ? hi : xv;
            float xn = xv - S * frcp(Gp);
            float xm = 0.5f * (lo + hi);
            bool ok = (xn > lo) && (xn < hi);
            xv = ok ? xn : xm;
        }

        // accurate polish: eval1 = Newton; eval2 = Newton + logdet.
        // pairwise rcp on 1/(1+E); exp clamp 60 so pair products can't overflow.
        const float NC2 = -2.f * LOG2E_F;
        float ld = 0.f;
#pragma unroll 1
        for (int it = 0; it < 2; ++it) {
            float cdf = 0.f, sf = 0.f, pdf = 0.f;
#pragma unroll
            for (int q = 0; q < 4; ++q) {
                float h0, h1, nm0, nm1, w0, w1;
                upk2(h0, h1, eh2[q]);
                upk2(nm0, nm1, nmh2[q]);
                upk2(w0, w1, w2p[q]);
                float at0 = fmaf(xv, h0, nm0);
                float at1 = fmaf(xv, h1, nm1);
                float E0 = fexp2(fminf(at0 * NC2, 60.f));
                float E1 = fexp2(fminf(at1 * NC2, 60.f));
                float d0 = 1.f + E0, d1 = 1.f + E1;
                float R = frcp(d0 * d1);
                float r0 = R * d1, r1 = R * d0;
                float a0 = w0 * r0, t10 = a0 * E0;
                float a1 = w1 * r1, t11 = a1 * E1;
                cdf += a0 + a1;
                sf += t10 + t11;
                pdf = fmaf((t10 * r0) * 2.f, h0, fmaf((t11 * r1) * 2.f, h1, pdf));
            }
            float lc = flogf_(cdf), lsf = flogf_(sf);
            if (it == 1) ld = flogf_(pdf) - lc - lsf + flogf_(wsum);
            float f = lc - lsf - y;
            xv -= f * cdf * sf * frcp(pdf) * rw;
        }

        z[(size_t)b * DD + za_off + i] = xv;
        red[(tb + (e << 4)) * 8 + ti] = ld;
    }

    __syncthreads();
    if (threadIdx.x < BTILE) {
        const float* rr = red + threadIdx.x * 8;
        float s = rr[0] + rr[1] + rr[2] + rr[3] + rr[4] + rr[5] + rr[6] + rr[7];
        g_ldpart[(size_t)blockIdx.x * BB + b0 + threadIdx.x] += s;
    }
}

// ---------------------------------------------------------------------------
// finalize log_q (coalesced over transposed ldpart)
// ---------------------------------------------------------------------------
__global__ void __launch_bounds__(256) fin_k(float* __restrict__ lq) {
    int b = blockIdx.x * 256 + threadIdx.x;
    if (b < BB) {
        float s = lq[b];
#pragma unroll 1
        for (int j = 0; j < NBI; ++j) s += g_ldpart[(size_t)j * BB + b];
        lq[b] = s;
    }
}

extern "C" void kernel_launch(void* const* d_in, const int* in_sizes, int n_in,
                              void* d_out, int out_size) {
    (void)in_sizes; (void)n_in; (void)out_size;
    const float* x    = (const float*)d_in[0];
    const float* eps  = (const float*)d_in[1];
    const float* Win  = (const float*)d_in[2];
    const float* bin  = (const float*)d_in[3];
    const float* W1   = (const float*)d_in[4];
    const float* b1   = (const float*)d_in[5];
    const float* W2   = (const float*)d_in[6];
    const float* b2   = (const float*)d_in[7];
    const float* Wout = (const float*)d_in[8];
    const float* bout = (const float*)d_in[9];

    float* z = (float*)d_out;              // (B, D) working/output z
    float* lq = z + (size_t)BB * DD;       // (B,) log_q

    size_t smemA = (size_t)(16 * WPAD + 1024 + 1024 + 64 + 64 + 16) * sizeof(float);
    static int smem_set = 0;
    if (!smem_set) {
        cudaFuncSetAttribute((const void*)cond_k, cudaFuncAttributeMaxDynamicSharedMemorySize,
                             (int)smemA);
        smem_set = 1;
    }

    init_k<<<BB, 256>>>(eps, z, lq);

    for (int l = LL - 1; l >= 0; --l) {
        int za_off = (l & 1) ? DHALF : 0;
        int zb_off = (l & 1) ? 0 : DHALF;
        cond_k<<<BB / 32, CBLK, smemA>>>(z, x,
                                         Win + (size_t)l * 1176 * 16,
                                         bin + (size_t)l * 16,
                                         W1 + (size_t)l * RR * 256,
                                         b1 + (size_t)l * RR * 16,
                                         W2 + (size_t)l * RR * 256,
                                         b2 + (size_t)l * RR * 16,
                                         zb_off);
        invert_k<<<dim3(NBI, BB / BTILE), 128>>>(z,
                                                 Wout + (size_t)l * 16 * 9408,
                                                 bout + (size_t)l * 9408,
                                                 za_off);
    }

    fin_k<<<BB / 256, 256>>>(lq);
}